// round 14
// baseline (speedup 1.0000x reference)
#include <cuda_runtime.h>
#include <mma.h>
#include <math.h>
#include <stdint.h>

using namespace nvcuda;

#define CB  32
#define CNS 4096
#define CD  256
#define CH  4
#define CDH 64
#define CL  6
#define CNQ 512
#define CNK 1024
#define SCALE_F 0.125f   // 1/sqrt(64), exact power of two
#define NKW (CNK/32)     // mask words per q row

// ------------------------- scratch (device globals; no allocs) -------------
__device__ float g_upd[CB*CNS*CD];
__device__ float g_q  [CB*CNQ*CD];     // qb (tf32); later hb_tf32
__device__ float g_k  [CB*CNK*CD];     // kb (tf32)
__device__ float g_Qp [CB*CNQ*CD];     // Q projected (tf32)
__device__ float g_Kp [CB*CNK*CD];
__device__ float g_Vp [CB*CNK*CD];
__device__ float g_ctx[CB*CNQ*CD];     // flash out (tf32)
__device__ float g_h  [CB*CNQ*CD];     // fp32 residual path
__device__ float g_t1 [CB*CNQ*CD];
__device__ float g_t2 [CB*CNQ*CD];
// pre-rounded (tf32) weights
__device__ float g_Wq [CD*CD];
__device__ float g_Wk [CD*CD];
__device__ float g_Wv [CD*CD];
__device__ float g_Wo [CD*CD];
__device__ float g_W1 [CD*CD];
__device__ float g_W2 [CD*CD];
__device__ uint32_t g_mbits[CL*CNQ*NKW];   // packed mask bits

// ------------------------- helpers ----------------------------------------
__device__ __forceinline__ float gelu_tanh(float x){
    float x3 = x*x*x;
    float t  = tanhf(0.7978845608028654f * (x + 0.044715f * x3));
    return 0.5f * x * (1.0f + t);
}
__device__ __forceinline__ float to_tf32(float x){
    return wmma::__float_to_tf32(x);
}
__device__ __forceinline__ void cp_async16_ca(void* dst_smem, const void* src){
    unsigned d = (unsigned)__cvta_generic_to_shared(dst_smem);
    asm volatile("cp.async.ca.shared.global [%0], [%1], 16;" :: "r"(d), "l"(src));
}
__device__ __forceinline__ void cp_commit(){
    asm volatile("cp.async.commit_group;" ::: "memory");
}
__device__ __forceinline__ void cp_wait1(){
    asm volatile("cp.async.wait_group 1;" ::: "memory");
}
__device__ __forceinline__ void cp_wait0(){
    asm volatile("cp.async.wait_group 0;" ::: "memory");
}

// ------------------------- init copy ---------------------------------------
__global__ void k_copy_upd(const float4* __restrict__ src){
    size_t i = (size_t)blockIdx.x * blockDim.x + threadIdx.x;
    ((float4*)g_upd)[i] = src[i];
}

// ------------------------- weight prep: round to tf32 ----------------------
__global__ void k_prep_w(const float* __restrict__ Wq, const float* __restrict__ Wk,
                         const float* __restrict__ Wv, const float* __restrict__ Wo,
                         const float* __restrict__ W1, const float* __restrict__ W2){
    int i = blockIdx.x * 256 + threadIdx.x;    // 0 .. 65535
    g_Wq[i] = to_tf32(Wq[i]);
    g_Wk[i] = to_tf32(Wk[i]);
    g_Wv[i] = to_tf32(Wv[i]);
    g_Wo[i] = to_tf32(Wo[i]);
    g_W1[i] = to_tf32(W1[i]);
    g_W2[i] = to_tf32(W2[i]);
}

// ------------------------- mask prep: floats -> bitmask --------------------
__global__ void k_prep_mask(const float* __restrict__ m){
    int i = blockIdx.x * 256 + threadIdx.x;
    const float4* src = (const float4*)m + (size_t)i*8;
    uint32_t bits = 0;
    #pragma unroll
    for(int j=0;j<8;j++){
        float4 v = src[j];
        bits |= (v.x > 0.5f ? 1u : 0u) << (j*4 + 0);
        bits |= (v.y > 0.5f ? 1u : 0u) << (j*4 + 1);
        bits |= (v.z > 0.5f ? 1u : 0u) << (j*4 + 2);
        bits |= (v.w > 0.5f ? 1u : 0u) << (j*4 + 3);
    }
    g_mbits[i] = bits;
}

// ------------------------- gather + LayerNorm (tf32 out) -------------------
__global__ void k_gather_ln(const float* __restrict__ upd,
                            const float* __restrict__ emb,
                            const int*   __restrict__ idx,
                            const float* __restrict__ sc,
                            const float* __restrict__ bi,
                            float* __restrict__ out, int N){
    __shared__ float sbuf[16];
    int row = blockIdx.x;
    int b = row / N, p = row - b*N;
    int node = idx[p];
    int t = threadIdx.x;
    float x = emb[(size_t)node*CD + t] + upd[((size_t)b*CNS + node)*CD + t];
    float s1 = x, s2 = x*x;
    #pragma unroll
    for(int o=16;o>0;o>>=1){
        s1 += __shfl_xor_sync(0xffffffffu, s1, o);
        s2 += __shfl_xor_sync(0xffffffffu, s2, o);
    }
    if((t&31)==0){ sbuf[t>>5]=s1; sbuf[8+(t>>5)]=s2; }
    __syncthreads();
    s1=0.f; s2=0.f;
    #pragma unroll
    for(int i=0;i<8;i++){ s1+=sbuf[i]; s2+=sbuf[8+i]; }
    float mean = s1 * (1.0f/CD);
    float var  = s2 * (1.0f/CD) - mean*mean;
    float rstd = rsqrtf(var + 1e-5f);
    out[(size_t)row*CD + t] = to_tf32((x-mean)*rstd*sc[t] + bi[t]);
}

// ------------------------- LayerNorm, dual output (fp32 + tf32) ------------
__global__ void k_ln2(const float* __restrict__ in,
                      const float* __restrict__ sc,
                      const float* __restrict__ bi,
                      float* __restrict__ out_f,
                      float* __restrict__ out_t){
    __shared__ float sbuf[16];
    int row = blockIdx.x;
    int t = threadIdx.x;
    float x = in[(size_t)row*CD + t];
    float s1 = x, s2 = x*x;
    #pragma unroll
    for(int o=16;o>0;o>>=1){
        s1 += __shfl_xor_sync(0xffffffffu, s1, o);
        s2 += __shfl_xor_sync(0xffffffffu, s2, o);
    }
    if((t&31)==0){ sbuf[t>>5]=s1; sbuf[8+(t>>5)]=s2; }
    __syncthreads();
    s1=0.f; s2=0.f;
    #pragma unroll
    for(int i=0;i<8;i++){ s1+=sbuf[i]; s2+=sbuf[8+i]; }
    float mean = s1 * (1.0f/CD);
    float var  = s2 * (1.0f/CD) - mean*mean;
    float rstd = rsqrtf(var + 1e-5f);
    float y = (x-mean)*rstd*sc[t] + bi[t];
    out_f[(size_t)row*CD + t] = y;
    out_t[(size_t)row*CD + t] = to_tf32(y);
}

// ===================== TF32 WMMA GEMM, 2-stage cp.async.ca =================
// C[M,256] = A[M,256] @ W[256,256] (+bias)(+gelu)(+rnd). Inputs pre-rounded
// tf32 -> staging is raw cp.async.ca (L1-cached, no staging regs, no cvt).
// 128x128 block, 8 warps (4x2), warp 32x64 = 2x4 m16n16k8 frags, 2 CTA/SM.
#define GSTG_A (128*36)
#define GSTG_B (32*132)
#define GSTG   (GSTG_A + GSTG_B)
#define GEMM_SMEM_FLOATS (2*GSTG)
__global__ void __launch_bounds__(256, 2)
k_gemm_tc(const float* __restrict__ A, const float* __restrict__ W,
          const float* __restrict__ bias, float* __restrict__ C,
          int act, int rnd){
    extern __shared__ __align__(16) float gsm[];
    int tid = threadIdx.x;
    int w = tid >> 5;
    int wy = w >> 1, wx = w & 1;           // 4 x 2 warps
    int bm0 = blockIdx.x * 128;
    int bn0 = blockIdx.y * 128;

    const int ar = tid >> 3, ac = (tid & 7) * 4;    // A: 32 rows/pass, x4
    const int br = tid >> 5, bc = (tid & 31) * 4;   // B: 8 rows/pass,  x4

    auto stage_tile = [&](int t, int buf){
        float* As_ = gsm + buf*GSTG;
        float* Bs_ = As_ + GSTG_A;
        int k0 = t*32;
        #pragma unroll
        for(int i=0;i<4;i++){
            int r = ar + i*32;
            cp_async16_ca(&As_[r*36 + ac], &A[(size_t)(bm0+r)*CD + k0 + ac]);
        }
        #pragma unroll
        for(int i=0;i<4;i++){
            int r = br + i*8;
            cp_async16_ca(&Bs_[r*132 + bc], &W[(size_t)(k0+r)*CD + bn0 + bc]);
        }
        cp_commit();
    };

    wmma::fragment<wmma::accumulator,16,16,8,float> acc[2][4];
    #pragma unroll
    for(int i=0;i<2;i++)
        #pragma unroll
        for(int j=0;j<4;j++) wmma::fill_fragment(acc[i][j], 0.0f);

    stage_tile(0, 0);

    #pragma unroll
    for(int t=0;t<8;t++){
        if(t+1 < 8) stage_tile(t+1, (t+1)&1);
        if(t+1 < 8) { cp_wait1(); } else { cp_wait0(); }   // tile t complete
        __syncthreads();                                    // visible to all

        float* As = gsm + (t&1)*GSTG;
        float* Bs = As + GSTG_A;
        #pragma unroll
        for(int ks=0;ks<4;ks++){
            wmma::fragment<wmma::matrix_a,16,16,8,wmma::precision::tf32,wmma::row_major> af[2];
            wmma::fragment<wmma::matrix_b,16,16,8,wmma::precision::tf32,wmma::row_major> bf[4];
            wmma::load_matrix_sync(af[0], &As[(wy*32)*36 + ks*8],    36);
            wmma::load_matrix_sync(af[1], &As[(wy*32+16)*36 + ks*8], 36);
            #pragma unroll
            for(int j=0;j<4;j++)
                wmma::load_matrix_sync(bf[j], &Bs[(ks*8)*132 + wx*64 + j*16], 132);
            #pragma unroll
            for(int i=0;i<2;i++)
                #pragma unroll
                for(int j=0;j<4;j++)
                    wmma::mma_sync(acc[i][j], af[i], bf[j], acc[i][j]);
        }
        __syncthreads();    // MMA done before this buffer is restaged
    }

    // ---- epilogue ----
    if(bias){
        float* BiasS = gsm;   // [16][132] overlay; all MMAs complete
        #pragma unroll
        for(int i=0;i<8;i++){
            int id = tid + i*256;      // 16x128
            int r = id >> 7, c = id & 127;
            BiasS[r*132 + c] = bias[bn0 + c];
        }
        __syncthreads();
        #pragma unroll
        for(int j=0;j<4;j++){
            wmma::fragment<wmma::accumulator,16,16,8,float> bfr;
            wmma::load_matrix_sync(bfr, &BiasS[wx*64 + j*16], 132, wmma::mem_row_major);
            #pragma unroll
            for(int i=0;i<2;i++)
                #pragma unroll
                for(int e=0;e<bfr.num_elements;e++)
                    acc[i][j].x[e] += bfr.x[e];
        }
    }
    #pragma unroll
    for(int i=0;i<2;i++)
        #pragma unroll
        for(int j=0;j<4;j++){
            if(act==1){
                #pragma unroll
                for(int e=0;e<acc[i][j].num_elements;e++)
                    acc[i][j].x[e] = gelu_tanh(acc[i][j].x[e]);
            }
            if(rnd){
                #pragma unroll
                for(int e=0;e<acc[i][j].num_elements;e++)
                    acc[i][j].x[e] = to_tf32(acc[i][j].x[e]);
            }
            wmma::store_matrix_sync(
                &C[(size_t)(bm0 + wy*32 + i*16)*CD + bn0 + wx*64 + j*16],
                acc[i][j], CD, wmma::mem_row_major);
        }
}

// ===================== fused flash attention (TF32 WMMA, bitmask) ==========
// grid (NQ/64, B*H), 256 thr = 8 warps. Q tile 64 rows, K tiles of 128.
// Inputs pre-rounded tf32 -> raw staging copies (Q scaled by 2^-3, exact).
// Mask via 1 LDG.32 bitword per lane per tile. Output pre-rounded tf32.
#define FLASH_SMEM_FLOATS (64*68 + 128*68 + 64*132 + 64*20)
__global__ void __launch_bounds__(256)
k_flash(const float* __restrict__ Q, const float* __restrict__ K,
        const float* __restrict__ V, const uint32_t* __restrict__ mbits,
        float* __restrict__ ctx){
    extern __shared__ __align__(16) float sm[];
    float* Qs  = sm;                    // [64][68]
    float* KVs = Qs  + 64*68;           // [128][68] K then V
    float* Ss  = KVs + 128*68;          // [64][132] scores -> probs
    float* aM  = Ss  + 64*132;          // [64][20]  per-row alpha / inv-denom

    int tid = threadIdx.x;
    int w = tid >> 5, lane = tid & 31;
    int wy = w >> 2, wx = w & 3;        // S phase: 2x4 warps (32q x 32k)
    int wq = w >> 1, wd = w & 1;        // PV phase: 4x2 warps (16q x 32d)
    int q0 = blockIdx.x * 64;
    int bh = blockIdx.y;
    int b = bh >> 2, h = bh & 3;

    const float* Qb = Q + ((size_t)(b*CNQ + q0))*CD + h*CDH;
    const float* Kb = K + ((size_t)b*CNK)*CD + h*CDH;
    const float* Vb = V + ((size_t)b*CNK)*CD + h*CDH;

    const int srow = w*8 + (lane >> 2);     // softmax: 4 lanes per row
    const int sqtr = lane & 3;              // 32-key quarter
    const uint32_t* mrow = mbits + (size_t)(q0+srow)*NKW;

    // ---- load Q (64x64), scale by 2^-3 (exact on tf32) ----
    #pragma unroll
    for(int i=0;i<4;i++){
        int id = tid + i*256;
        int r = id >> 4, c4 = id & 15;
        float4 v = *(const float4*)&Qb[(size_t)r*CD + c4*4];
        float* d = &Qs[r*68 + c4*4];
        d[0]=v.x*SCALE_F; d[1]=v.y*SCALE_F; d[2]=v.z*SCALE_F; d[3]=v.w*SCALE_F;
    }
    // ---- load K tile 0 (raw) ----
    #pragma unroll
    for(int i=0;i<8;i++){
        int id = tid + i*256;
        int r = id >> 4, c4 = id & 15;
        *(float4*)&KVs[r*68 + c4*4] = *(const float4*)&Kb[(size_t)r*CD + c4*4];
    }

    float m_run = -INFINITY, d_run = 0.f;

    wmma::fragment<wmma::accumulator,16,16,8,float> o[2];
    wmma::fill_fragment(o[0], 0.0f);
    wmma::fill_fragment(o[1], 0.0f);

    for(int k0=0; k0<CNK; k0+=128){
        __syncthreads();      // (a) KVs holds K for this tile

        // mask word + V tile staged early (overlap with S-MMA)
        uint32_t mb = mrow[(k0>>5) + sqtr];
        float4 vreg[8];
        #pragma unroll
        for(int i=0;i<8;i++){
            int id = tid + i*256;
            int r = id >> 4, c4 = id & 15;
            vreg[i] = *(const float4*)&Vb[(size_t)(k0+r)*CD + c4*4];
        }

        // ---- S = Qs @ K^T  (64x128) ----
        {
            wmma::fragment<wmma::accumulator,16,16,8,float> s[2][2];
            #pragma unroll
            for(int i=0;i<2;i++)
                #pragma unroll
                for(int j=0;j<2;j++) wmma::fill_fragment(s[i][j], 0.0f);
            #pragma unroll
            for(int d8=0; d8<CDH; d8+=8){
                wmma::fragment<wmma::matrix_a,16,16,8,wmma::precision::tf32,wmma::row_major> af[2];
                wmma::fragment<wmma::matrix_b,16,16,8,wmma::precision::tf32,wmma::col_major> bf[2];
                wmma::load_matrix_sync(af[0], &Qs[(wy*32)*68 + d8],      68);
                wmma::load_matrix_sync(af[1], &Qs[(wy*32+16)*68 + d8],   68);
                wmma::load_matrix_sync(bf[0], &KVs[(wx*32)*68 + d8],     68);
                wmma::load_matrix_sync(bf[1], &KVs[(wx*32+16)*68 + d8],  68);
                #pragma unroll
                for(int i=0;i<2;i++)
                    #pragma unroll
                    for(int j=0;j<2;j++)
                        wmma::mma_sync(s[i][j], af[i], bf[j], s[i][j]);
            }
            #pragma unroll
            for(int i=0;i<2;i++)
                #pragma unroll
                for(int j=0;j<2;j++)
                    wmma::store_matrix_sync(&Ss[(wy*32+i*16)*132 + wx*32 + j*16],
                                            s[i][j], 132, wmma::mem_row_major);
        }
        __syncthreads();      // (b) S done; KVs free for V

        // ---- store staged V (raw) ----
        #pragma unroll
        for(int i=0;i<8;i++){
            int id = tid + i*256;
            int r = id >> 4, c4 = id & 15;
            *(float4*)&KVs[r*68 + c4*4] = vreg[i];
        }

        // ---- masked online softmax: 4 lanes/row, 32 keys/lane, bitmask ----
        {
            float* sptr = &Ss[srow*132 + sqtr*32];
            float4 s4[8];
            #pragma unroll
            for(int i=0;i<8;i++) s4[i] = *(float4*)&sptr[i*4];

            float mx = -INFINITY;
            #pragma unroll
            for(int i=0;i<8;i++){
                s4[i].x = ((mb>>(4*i  ))&1u) ? s4[i].x : -1e9f;
                s4[i].y = ((mb>>(4*i+1))&1u) ? s4[i].y : -1e9f;
                s4[i].z = ((mb>>(4*i+2))&1u) ? s4[i].z : -1e9f;
                s4[i].w = ((mb>>(4*i+3))&1u) ? s4[i].w : -1e9f;
                mx = fmaxf(mx, fmaxf(fmaxf(s4[i].x,s4[i].y), fmaxf(s4[i].z,s4[i].w)));
            }
            mx = fmaxf(mx, __shfl_xor_sync(0xffffffffu, mx, 1));
            mx = fmaxf(mx, __shfl_xor_sync(0xffffffffu, mx, 2));

            float mn    = fmaxf(m_run, mx);
            float alpha = __expf(m_run - mn);
            float ps = 0.f;
            #pragma unroll
            for(int i=0;i<8;i++){
                float p0 = __expf(s4[i].x - mn), p1 = __expf(s4[i].y - mn);
                float p2 = __expf(s4[i].z - mn), p3 = __expf(s4[i].w - mn);
                ps += (p0+p1)+(p2+p3);
                s4[i].x = to_tf32(p0); s4[i].y = to_tf32(p1);
                s4[i].z = to_tf32(p2); s4[i].w = to_tf32(p3);
            }
            ps += __shfl_xor_sync(0xffffffffu, ps, 1);
            ps += __shfl_xor_sync(0xffffffffu, ps, 2);

            d_run = d_run*alpha + ps;
            m_run = mn;

            #pragma unroll
            for(int i=0;i<8;i++) *(float4*)&sptr[i*4] = s4[i];
            *(float4*)&aM[srow*20 + sqtr*4] = make_float4(alpha, alpha, alpha, alpha);
        }

        // stage next K into regs (overlaps PV)
        float4 kreg[8];
        bool has_next = (k0 + 128 < CNK);
        if(has_next){
            #pragma unroll
            for(int i=0;i<8;i++){
                int id = tid + i*256;
                int r = id >> 4, c4 = id & 15;
                kreg[i] = *(const float4*)&Kb[(size_t)(k0+128+r)*CD + c4*4];
            }
        }
        __syncthreads();      // (c) probs + V + alpha visible

        // ---- O = O*alpha + P @ V ----
        {
            wmma::fragment<wmma::accumulator,16,16,8,float> afr;
            wmma::load_matrix_sync(afr, &aM[(wq*16)*20], 20, wmma::mem_row_major);
            #pragma unroll
            for(int e=0;e<afr.num_elements;e++){
                o[0].x[e] *= afr.x[e];
                o[1].x[e] *= afr.x[e];
            }
            #pragma unroll
            for(int ks=0;ks<16;ks++){
                wmma::fragment<wmma::matrix_a,16,16,8,wmma::precision::tf32,wmma::row_major> pa;
                wmma::fragment<wmma::matrix_b,16,16,8,wmma::precision::tf32,wmma::row_major> vb[2];
                wmma::load_matrix_sync(pa, &Ss[(wq*16)*132 + ks*8], 132);
                wmma::load_matrix_sync(vb[0], &KVs[(ks*8)*68 + wd*32],      68);
                wmma::load_matrix_sync(vb[1], &KVs[(ks*8)*68 + wd*32 + 16], 68);
                wmma::mma_sync(o[0], pa, vb[0], o[0]);
                wmma::mma_sync(o[1], pa, vb[1], o[1]);
            }
        }
        __syncthreads();      // (d) PV done reading KVs(V)

        if(has_next){
            #pragma unroll
            for(int i=0;i<8;i++){
                int id = tid + i*256;
                int r = id >> 4, c4 = id & 15;
                *(float4*)&KVs[r*68 + c4*4] = kreg[i];
            }
        }
    }

    // ---- finalize: divide by denom, round to tf32, store ----
    *(float4*)&aM[srow*20 + sqtr*4] =
        make_float4(1.0f/d_run, 1.0f/d_run, 1.0f/d_run, 1.0f/d_run);
    __syncthreads();
    {
        wmma::fragment<wmma::accumulator,16,16,8,float> ifr;
        wmma::load_matrix_sync(ifr, &aM[(wq*16)*20], 20, wmma::mem_row_major);
        #pragma unroll
        for(int e=0;e<ifr.num_elements;e++){
            o[0].x[e] = to_tf32(o[0].x[e] * ifr.x[e]);
            o[1].x[e] = to_tf32(o[1].x[e] * ifr.x[e]);
        }
        float* cb = ctx + ((size_t)(b*CNQ + q0 + wq*16))*CD + h*CDH + wd*32;
        wmma::store_matrix_sync(cb,      o[0], CD, wmma::mem_row_major);
        wmma::store_matrix_sync(cb + 16, o[1], CD, wmma::mem_row_major);
    }
}

// ------------------------- h+ffn, double LN, scatter-add -------------------
__global__ void k_final(const float* __restrict__ h, const float* __restrict__ t2,
                        const float* __restrict__ os, const float* __restrict__ ob,
                        const float* __restrict__ es, const float* __restrict__ eb,
                        const int*   __restrict__ qidx,
                        float* __restrict__ upd, float* __restrict__ outp){
    __shared__ float sbuf[16];
    int row = blockIdx.x;
    int b = row >> 9, p = row & (CNQ-1);
    int t = threadIdx.x;
    float x = h[(size_t)row*CD + t] + t2[(size_t)row*CD + t];

    float s1 = x, s2 = x*x;
    #pragma unroll
    for(int o=16;o>0;o>>=1){
        s1 += __shfl_xor_sync(0xffffffffu, s1, o);
        s2 += __shfl_xor_sync(0xffffffffu, s2, o);
    }
    if((t&31)==0){ sbuf[t>>5]=s1; sbuf[8+(t>>5)]=s2; }
    __syncthreads();
    s1=0.f; s2=0.f;
    #pragma unroll
    for(int i=0;i<8;i++){ s1+=sbuf[i]; s2+=sbuf[8+i]; }
    float mean = s1*(1.0f/CD);
    float var  = s2*(1.0f/CD) - mean*mean;
    float rstd = rsqrtf(var + 1e-5f);
    float y = (x-mean)*rstd*os[t] + ob[t];
    __syncthreads();

    s1 = y; s2 = y*y;
    #pragma unroll
    for(int o=16;o>0;o>>=1){
        s1 += __shfl_xor_sync(0xffffffffu, s1, o);
        s2 += __shfl_xor_sync(0xffffffffu, s2, o);
    }
    if((t&31)==0){ sbuf[t>>5]=s1; sbuf[8+(t>>5)]=s2; }
    __syncthreads();
    s1=0.f; s2=0.f;
    #pragma unroll
    for(int i=0;i<8;i++){ s1+=sbuf[i]; s2+=sbuf[8+i]; }
    float mean2 = s1*(1.0f/CD);
    float var2  = s2*(1.0f/CD) - mean2*mean2;
    float rstd2 = rsqrtf(var2 + 1e-5f);
    float res = (y-mean2)*rstd2*es[t] + eb[t];

    int node = qidx[p];
    size_t off = ((size_t)(b*CNS + node))*CD + t;
    atomicAdd(&upd[off],  res);
    atomicAdd(&outp[off], res);
}

// ------------------------- launch ------------------------------------------
extern "C" void kernel_launch(void* const* d_in, const int* in_sizes, int n_in,
                              void* d_out, int out_size){
    const float* in_upd  = (const float*)d_in[0];
    const float* emb     = (const float*)d_in[1];
    const float* maskL   = (const float*)d_in[2];
    const float* Wq      = (const float*)d_in[3];
    const float* Wk      = (const float*)d_in[4];
    const float* Wv      = (const float*)d_in[5];
    const float* Wo      = (const float*)d_in[6];
    const float* W1      = (const float*)d_in[7];
    const float* b1      = (const float*)d_in[8];
    const float* W2      = (const float*)d_in[9];
    const float* b2      = (const float*)d_in[10];
    const float* sys_s   = (const float*)d_in[11];
    const float* sys_b   = (const float*)d_in[12];
    const float* eff_s   = (const float*)d_in[13];
    const float* eff_b   = (const float*)d_in[14];
    const float* in_s    = (const float*)d_in[15];
    const float* in_b    = (const float*)d_in[16];
    const float* out_s   = (const float*)d_in[17];
    const float* out_b   = (const float*)d_in[18];
    const int*   qidxL   = (const int*)d_in[19];
    const int*   kidxL   = (const int*)d_in[20];
    float* outp = (float*)d_out;

    float *upd,*qb,*kb,*Qb,*Kb,*Vb,*ctx,*hb,*t1,*t2;
    float *wq,*wk,*wv,*wo,*w1,*w2;
    uint32_t* mbits;
    cudaGetSymbolAddress((void**)&upd, g_upd);
    cudaGetSymbolAddress((void**)&qb,  g_q);
    cudaGetSymbolAddress((void**)&kb,  g_k);
    cudaGetSymbolAddress((void**)&Qb,  g_Qp);
    cudaGetSymbolAddress((void**)&Kb,  g_Kp);
    cudaGetSymbolAddress((void**)&Vb,  g_Vp);
    cudaGetSymbolAddress((void**)&ctx, g_ctx);
    cudaGetSymbolAddress((void**)&hb,  g_h);
    cudaGetSymbolAddress((void**)&t1,  g_t1);
    cudaGetSymbolAddress((void**)&t2,  g_t2);
    cudaGetSymbolAddress((void**)&wq,  g_Wq);
    cudaGetSymbolAddress((void**)&wk,  g_Wk);
    cudaGetSymbolAddress((void**)&wv,  g_Wv);
    cudaGetSymbolAddress((void**)&wo,  g_Wo);
    cudaGetSymbolAddress((void**)&w1,  g_W1);
    cudaGetSymbolAddress((void**)&w2,  g_W2);
    cudaGetSymbolAddress((void**)&mbits, g_mbits);

    const int flash_smem = FLASH_SMEM_FLOATS * (int)sizeof(float);  // ~91 KB
    const int gemm_smem  = GEMM_SMEM_FLOATS  * (int)sizeof(float);  // ~71 KB
    cudaFuncSetAttribute(k_flash,   cudaFuncAttributeMaxDynamicSharedMemorySize,
                         flash_smem);
    cudaFuncSetAttribute(k_gemm_tc, cudaFuncAttributeMaxDynamicSharedMemorySize,
                         gemm_smem);

    cudaMemsetAsync(d_out, 0, (size_t)out_size * sizeof(float));
    k_copy_upd<<<(CB*CNS*CD/4)/256, 256>>>((const float4*)in_upd);
    k_prep_w<<<256, 256>>>(Wq, Wk, Wv, Wo, W1, W2);
    k_prep_mask<<<(CL*CNQ*NKW)/256, 256>>>(maskL);

    for(int l=0;l<CL;l++){
        const int* qi = qidxL + l*CNQ;
        const int* ki = kidxL + l*CNK;
        const uint32_t* mb = mbits + (size_t)l*CNQ*NKW;

        k_gather_ln<<<CB*CNQ, 256>>>(upd, emb, qi, sys_s, sys_b, qb, CNQ);
        k_gather_ln<<<CB*CNK, 256>>>(upd, emb, ki, sys_s, sys_b, kb, CNK);

        k_gemm_tc<<<dim3(CB*CNQ/128, 2), 256, gemm_smem>>>(qb, wq, nullptr, Qb, 0, 1);
        k_gemm_tc<<<dim3(CB*CNK/128, 2), 256, gemm_smem>>>(kb, wk, nullptr, Kb, 0, 1);
        k_gemm_tc<<<dim3(CB*CNK/128, 2), 256, gemm_smem>>>(kb, wv, nullptr, Vb, 0, 1);

        k_flash<<<dim3(CNQ/64, CB*CH), 256, flash_smem>>>(Qb, Kb, Vb, mb, ctx);

        k_gemm_tc<<<dim3(CB*CNQ/128, 2), 256, gemm_smem>>>(ctx, wo, nullptr, t1, 0, 0);
        k_ln2<<<CB*CNQ, 256>>>(t1, in_s, in_b, hb, qb);   // qb reused as hb_tf32

        k_gemm_tc<<<dim3(CB*CNQ/128, 2), 256, gemm_smem>>>(qb, w1, b1, t1, 1, 1);
        k_gemm_tc<<<dim3(CB*CNQ/128, 2), 256, gemm_smem>>>(t1, w2, b2, t2, 0, 0);

        k_final<<<CB*CNQ, 256>>>(hb, t2, out_s, out_b, eff_s, eff_b,
                                 qi, upd, outp);
    }
}

// round 15
// speedup vs baseline: 1.6741x; 1.6741x over previous
#include <cuda_runtime.h>
#include <mma.h>
#include <math.h>
#include <stdint.h>

using namespace nvcuda;

#define CB  32
#define CNS 4096
#define CD  256
#define CH  4
#define CDH 64
#define CL  6
#define CNQ 512
#define CNK 1024
#define SCALE_F 0.125f   // 1/sqrt(64)
#define NKW (CNK/32)     // mask words per q row

// ------------------------- scratch (device globals; no allocs) -------------
__device__ float g_upd[CB*CNS*CD];
__device__ float g_q  [CB*CNQ*CD];
__device__ float g_k  [CB*CNK*CD];
__device__ float g_Qp [CB*CNQ*CD];
__device__ float g_Kp [CB*CNK*CD];
__device__ float g_Vp [CB*CNK*CD];
__device__ float g_ctx[CB*CNQ*CD];
__device__ float g_h  [CB*CNQ*CD];
__device__ float g_t1 [CB*CNQ*CD];
__device__ float g_t2 [CB*CNQ*CD];
__device__ uint32_t g_mbits[CL*CNQ*NKW];   // packed mask bits

// ------------------------- helpers ----------------------------------------
__device__ __forceinline__ float gelu_tanh(float x){
    float x3 = x*x*x;
    float t  = tanhf(0.7978845608028654f * (x + 0.044715f * x3));
    return 0.5f * x * (1.0f + t);
}
__device__ __forceinline__ float to_tf32(float x){
    return wmma::__float_to_tf32(x);
}

// ------------------------- init copy ---------------------------------------
__global__ void k_copy_upd(const float4* __restrict__ src){
    size_t i = (size_t)blockIdx.x * blockDim.x + threadIdx.x;
    ((float4*)g_upd)[i] = src[i];
}

// ------------------------- mask prep: floats -> bitmask --------------------
__global__ void k_prep_mask(const float* __restrict__ m){
    int i = blockIdx.x * 256 + threadIdx.x;     // word idx, CL*CNQ*NKW total
    const float4* src = (const float4*)m + (size_t)i*8;
    uint32_t bits = 0;
    #pragma unroll
    for(int j=0;j<8;j++){
        float4 v = src[j];
        bits |= (v.x > 0.5f ? 1u : 0u) << (j*4 + 0);
        bits |= (v.y > 0.5f ? 1u : 0u) << (j*4 + 1);
        bits |= (v.z > 0.5f ? 1u : 0u) << (j*4 + 2);
        bits |= (v.w > 0.5f ? 1u : 0u) << (j*4 + 3);
    }
    g_mbits[i] = bits;
}

// ------------------------- gather + LayerNorm ------------------------------
__global__ void k_gather_ln(const float* __restrict__ upd,
                            const float* __restrict__ emb,
                            const int*   __restrict__ idx,
                            const float* __restrict__ sc,
                            const float* __restrict__ bi,
                            float* __restrict__ out, int N){
    __shared__ float sbuf[16];
    int row = blockIdx.x;
    int b = row / N, p = row - b*N;
    int node = idx[p];
    int t = threadIdx.x;
    float x = emb[(size_t)node*CD + t] + upd[((size_t)b*CNS + node)*CD + t];
    float s1 = x, s2 = x*x;
    #pragma unroll
    for(int o=16;o>0;o>>=1){
        s1 += __shfl_xor_sync(0xffffffffu, s1, o);
        s2 += __shfl_xor_sync(0xffffffffu, s2, o);
    }
    if((t&31)==0){ sbuf[t>>5]=s1; sbuf[8+(t>>5)]=s2; }
    __syncthreads();
    s1=0.f; s2=0.f;
    #pragma unroll
    for(int i=0;i<8;i++){ s1+=sbuf[i]; s2+=sbuf[8+i]; }
    float mean = s1 * (1.0f/CD);
    float var  = s2 * (1.0f/CD) - mean*mean;
    float rstd = rsqrtf(var + 1e-5f);
    out[(size_t)row*CD + t] = (x-mean)*rstd*sc[t] + bi[t];
}

// ------------------------- plain row LayerNorm -----------------------------
__global__ void k_ln(const float* __restrict__ in,
                     const float* __restrict__ sc,
                     const float* __restrict__ bi,
                     float* __restrict__ out){
    __shared__ float sbuf[16];
    int row = blockIdx.x;
    int t = threadIdx.x;
    float x = in[(size_t)row*CD + t];
    float s1 = x, s2 = x*x;
    #pragma unroll
    for(int o=16;o>0;o>>=1){
        s1 += __shfl_xor_sync(0xffffffffu, s1, o);
        s2 += __shfl_xor_sync(0xffffffffu, s2, o);
    }
    if((t&31)==0){ sbuf[t>>5]=s1; sbuf[8+(t>>5)]=s2; }
    __syncthreads();
    s1=0.f; s2=0.f;
    #pragma unroll
    for(int i=0;i<8;i++){ s1+=sbuf[i]; s2+=sbuf[8+i]; }
    float mean = s1 * (1.0f/CD);
    float var  = s2 * (1.0f/CD) - mean*mean;
    float rstd = rsqrtf(var + 1e-5f);
    out[(size_t)row*CD + t] = (x-mean)*rstd*sc[t] + bi[t];
}

// ===================== TF32 WMMA dense GEMM (round-6 proven) ===============
// C[M,256] = A[M,256] @ W[256,256] (+bias)(+gelu). 8 warps as 4x2,
// warp tile 32x64 = 2x4 m16n16k8 frags. Static 44KB smem, sync staging.
__global__ void __launch_bounds__(256)
k_gemm_tc(const float* __restrict__ A, const float* __restrict__ W,
          const float* __restrict__ bias, float* __restrict__ C, int act){
    __shared__ __align__(16) float As[128][36];
    __shared__ __align__(16) float Bs[32][132];
    __shared__ __align__(16) float BiasS[16][132];
    int tid = threadIdx.x;
    int w = tid >> 5;
    int wy = w >> 1, wx = w & 1;           // 4 x 2 warps
    int bm0 = blockIdx.x * 128;
    int bn0 = blockIdx.y * 128;

    wmma::fragment<wmma::accumulator,16,16,8,float> acc[2][4];
    #pragma unroll
    for(int i=0;i<2;i++)
        #pragma unroll
        for(int j=0;j<4;j++) wmma::fill_fragment(acc[i][j], 0.0f);

    for(int k0=0;k0<CD;k0+=32){
        // A tile 128x32
        #pragma unroll
        for(int i=0;i<4;i++){
            int id = tid + i*256;
            int r = id >> 3, c4 = id & 7;
            float4 v = *(const float4*)&A[(size_t)(bm0+r)*CD + k0 + c4*4];
            float* d = &As[r][c4*4];
            d[0]=to_tf32(v.x); d[1]=to_tf32(v.y); d[2]=to_tf32(v.z); d[3]=to_tf32(v.w);
        }
        // B tile 32x128
        #pragma unroll
        for(int i=0;i<4;i++){
            int id = tid + i*256;
            int r = id >> 5, c4 = id & 31;
            float4 v = *(const float4*)&W[(size_t)(k0+r)*CD + bn0 + c4*4];
            float* d = &Bs[r][c4*4];
            d[0]=to_tf32(v.x); d[1]=to_tf32(v.y); d[2]=to_tf32(v.z); d[3]=to_tf32(v.w);
        }
        __syncthreads();
        #pragma unroll
        for(int ks=0;ks<4;ks++){
            wmma::fragment<wmma::matrix_a,16,16,8,wmma::precision::tf32,wmma::row_major> af[2];
            wmma::fragment<wmma::matrix_b,16,16,8,wmma::precision::tf32,wmma::row_major> bf[4];
            wmma::load_matrix_sync(af[0], &As[wy*32][ks*8],    36);
            wmma::load_matrix_sync(af[1], &As[wy*32+16][ks*8], 36);
            #pragma unroll
            for(int j=0;j<4;j++)
                wmma::load_matrix_sync(bf[j], &Bs[ks*8][wx*64 + j*16], 132);
            #pragma unroll
            for(int i=0;i<2;i++)
                #pragma unroll
                for(int j=0;j<4;j++)
                    wmma::mma_sync(acc[i][j], af[i], bf[j], acc[i][j]);
        }
        __syncthreads();
    }

    if(bias){
        #pragma unroll
        for(int i=0;i<8;i++){
            int id = tid + i*256;      // 16x128
            int r = id >> 7, c = id & 127;
            BiasS[r][c] = bias[bn0 + c];
        }
        __syncthreads();
        #pragma unroll
        for(int j=0;j<4;j++){
            wmma::fragment<wmma::accumulator,16,16,8,float> bfr;
            wmma::load_matrix_sync(bfr, &BiasS[0][wx*64 + j*16], 132, wmma::mem_row_major);
            #pragma unroll
            for(int i=0;i<2;i++)
                #pragma unroll
                for(int e=0;e<bfr.num_elements;e++)
                    acc[i][j].x[e] += bfr.x[e];
        }
    }
    if(act==1){
        #pragma unroll
        for(int i=0;i<2;i++)
            #pragma unroll
            for(int j=0;j<4;j++)
                #pragma unroll
                for(int e=0;e<acc[i][j].num_elements;e++)
                    acc[i][j].x[e] = gelu_tanh(acc[i][j].x[e]);
    }
    #pragma unroll
    for(int i=0;i<2;i++)
        #pragma unroll
        for(int j=0;j<4;j++)
            wmma::store_matrix_sync(
                &C[(size_t)(bm0 + wy*32 + i*16)*CD + bn0 + wx*64 + j*16],
                acc[i][j], CD, wmma::mem_row_major);
}

// ===================== fused flash attention (512 thr, 128 q-rows) =========
// grid (NQ/128, B*H), 512 thr = 16 warps. Q tile 128 rows, K tiles of 128.
// 16 warps/SM (vs 8) doubles latency hiding in every sync-separated phase;
// half the CTAs halves total sync count. Bitmask mask: 1 LDG.32/lane/tile.
#define FLASH_SMEM_FLOATS (128*68 + 128*68 + 128*132 + 128*20)
__global__ void __launch_bounds__(512)
k_flash(const float* __restrict__ Q, const float* __restrict__ K,
        const float* __restrict__ V, const uint32_t* __restrict__ mbits,
        float* __restrict__ ctx){
    extern __shared__ __align__(16) float sm[];
    float* Qs  = sm;                    // [128][68]  q (pre-scaled, tf32)
    float* KVs = Qs  + 128*68;          // [128][68]  K then V (tf32)
    float* Ss  = KVs + 128*68;          // [128][132] scores -> probs
    float* aM  = Ss  + 128*132;         // [128][20]  per-row alpha / inv-denom

    int tid = threadIdx.x;
    int w = tid >> 5, lane = tid & 31;
    int wy = w >> 2, wx = w & 3;        // S phase: 4x4 warps (32q x 32k)
    int wq = w >> 1, wd = w & 1;        // PV phase: 8x2 warps (16q x 32d)
    int q0 = blockIdx.x * 128;
    int bh = blockIdx.y;
    int b = bh >> 2, h = bh & 3;

    const float* Qb = Q + ((size_t)(b*CNQ + q0))*CD + h*CDH;
    const float* Kb = K + ((size_t)b*CNK)*CD + h*CDH;
    const float* Vb = V + ((size_t)b*CNK)*CD + h*CDH;

    const int srow = w*8 + (lane >> 2);     // softmax: 4 lanes/row, rows 0..127
    const int sqtr = lane & 3;              // 32-key quarter
    const uint32_t* mrow = mbits + (size_t)(q0+srow)*NKW;

    // ---- load Q (128x64), pre-scaled ----
    #pragma unroll
    for(int i=0;i<4;i++){
        int id = tid + i*512;
        int r = id >> 4, c4 = id & 15;
        float4 v = *(const float4*)&Qb[(size_t)r*CD + c4*4];
        float* d = &Qs[r*68 + c4*4];
        d[0]=to_tf32(v.x*SCALE_F); d[1]=to_tf32(v.y*SCALE_F);
        d[2]=to_tf32(v.z*SCALE_F); d[3]=to_tf32(v.w*SCALE_F);
    }
    // ---- load K tile 0 ----
    #pragma unroll
    for(int i=0;i<4;i++){
        int id = tid + i*512;
        int r = id >> 4, c4 = id & 15;
        float4 v = *(const float4*)&Kb[(size_t)r*CD + c4*4];
        float* d = &KVs[r*68 + c4*4];
        d[0]=to_tf32(v.x); d[1]=to_tf32(v.y); d[2]=to_tf32(v.z); d[3]=to_tf32(v.w);
    }

    float m_run = -INFINITY, d_run = 0.f;   // per-lane, for row `srow`

    wmma::fragment<wmma::accumulator,16,16,8,float> o[2];
    wmma::fill_fragment(o[0], 0.0f);
    wmma::fill_fragment(o[1], 0.0f);

    for(int k0=0; k0<CNK; k0+=128){
        __syncthreads();      // (a) KVs holds K for this tile

        // mask word + V tile staged early (overlap with S-MMA)
        uint32_t mb = mrow[(k0>>5) + sqtr];
        float4 vreg[4];
        #pragma unroll
        for(int i=0;i<4;i++){
            int id = tid + i*512;
            int r = id >> 4, c4 = id & 15;
            vreg[i] = *(const float4*)&Vb[(size_t)(k0+r)*CD + c4*4];
        }

        // ---- S = Qs @ K^T  (128x128), warp = 32q x 32k ----
        {
            wmma::fragment<wmma::accumulator,16,16,8,float> s[2][2];
            #pragma unroll
            for(int i=0;i<2;i++)
                #pragma unroll
                for(int j=0;j<2;j++) wmma::fill_fragment(s[i][j], 0.0f);
            #pragma unroll
            for(int d8=0; d8<CDH; d8+=8){
                wmma::fragment<wmma::matrix_a,16,16,8,wmma::precision::tf32,wmma::row_major> af[2];
                wmma::fragment<wmma::matrix_b,16,16,8,wmma::precision::tf32,wmma::col_major> bf[2];
                wmma::load_matrix_sync(af[0], &Qs[(wy*32)*68 + d8],      68);
                wmma::load_matrix_sync(af[1], &Qs[(wy*32+16)*68 + d8],   68);
                wmma::load_matrix_sync(bf[0], &KVs[(wx*32)*68 + d8],     68);
                wmma::load_matrix_sync(bf[1], &KVs[(wx*32+16)*68 + d8],  68);
                #pragma unroll
                for(int i=0;i<2;i++)
                    #pragma unroll
                    for(int j=0;j<2;j++)
                        wmma::mma_sync(s[i][j], af[i], bf[j], s[i][j]);
            }
            #pragma unroll
            for(int i=0;i<2;i++)
                #pragma unroll
                for(int j=0;j<2;j++)
                    wmma::store_matrix_sync(&Ss[(wy*32+i*16)*132 + wx*32 + j*16],
                                            s[i][j], 132, wmma::mem_row_major);
        }
        __syncthreads();      // (b) S done; KVs free for V

        // ---- store staged V ----
        #pragma unroll
        for(int i=0;i<4;i++){
            int id = tid + i*512;
            int r = id >> 4, c4 = id & 15;
            float* d = &KVs[r*68 + c4*4];
            d[0]=to_tf32(vreg[i].x); d[1]=to_tf32(vreg[i].y);
            d[2]=to_tf32(vreg[i].z); d[3]=to_tf32(vreg[i].w);
        }

        // ---- masked online softmax: 4 lanes/row, 32 keys/lane, bitmask ----
        {
            float* sptr = &Ss[srow*132 + sqtr*32];
            float4 s4[8];
            #pragma unroll
            for(int i=0;i<8;i++) s4[i] = *(float4*)&sptr[i*4];

            float mx = -INFINITY;
            #pragma unroll
            for(int i=0;i<8;i++){
                s4[i].x = ((mb>>(4*i  ))&1u) ? s4[i].x : -1e9f;
                s4[i].y = ((mb>>(4*i+1))&1u) ? s4[i].y : -1e9f;
                s4[i].z = ((mb>>(4*i+2))&1u) ? s4[i].z : -1e9f;
                s4[i].w = ((mb>>(4*i+3))&1u) ? s4[i].w : -1e9f;
                mx = fmaxf(mx, fmaxf(fmaxf(s4[i].x,s4[i].y), fmaxf(s4[i].z,s4[i].w)));
            }
            mx = fmaxf(mx, __shfl_xor_sync(0xffffffffu, mx, 1));
            mx = fmaxf(mx, __shfl_xor_sync(0xffffffffu, mx, 2));

            float mn    = fmaxf(m_run, mx);
            float alpha = __expf(m_run - mn);
            float ps = 0.f;
            #pragma unroll
            for(int i=0;i<8;i++){
                float p0 = __expf(s4[i].x - mn), p1 = __expf(s4[i].y - mn);
                float p2 = __expf(s4[i].z - mn), p3 = __expf(s4[i].w - mn);
                ps += (p0+p1)+(p2+p3);
                s4[i].x = to_tf32(p0); s4[i].y = to_tf32(p1);
                s4[i].z = to_tf32(p2); s4[i].w = to_tf32(p3);
            }
            ps += __shfl_xor_sync(0xffffffffu, ps, 1);
            ps += __shfl_xor_sync(0xffffffffu, ps, 2);

            d_run = d_run*alpha + ps;
            m_run = mn;

            #pragma unroll
            for(int i=0;i<8;i++) *(float4*)&sptr[i*4] = s4[i];
            *(float4*)&aM[srow*20 + sqtr*4] = make_float4(alpha, alpha, alpha, alpha);
        }

        // stage next K into regs (overlaps PV)
        float4 kreg[4];
        bool has_next = (k0 + 128 < CNK);
        if(has_next){
            #pragma unroll
            for(int i=0;i<4;i++){
                int id = tid + i*512;
                int r = id >> 4, c4 = id & 15;
                kreg[i] = *(const float4*)&Kb[(size_t)(k0+128+r)*CD + c4*4];
            }
        }
        __syncthreads();      // (c) probs + V + alpha visible

        // ---- O = O*alpha + P @ V ; warp = 16q x 32d ----
        {
            wmma::fragment<wmma::accumulator,16,16,8,float> afr;
            wmma::load_matrix_sync(afr, &aM[(wq*16)*20], 20, wmma::mem_row_major);
            #pragma unroll
            for(int e=0;e<afr.num_elements;e++){
                o[0].x[e] *= afr.x[e];
                o[1].x[e] *= afr.x[e];
            }
            #pragma unroll
            for(int ks=0;ks<16;ks++){
                wmma::fragment<wmma::matrix_a,16,16,8,wmma::precision::tf32,wmma::row_major> pa;
                wmma::fragment<wmma::matrix_b,16,16,8,wmma::precision::tf32,wmma::row_major> vb[2];
                wmma::load_matrix_sync(pa, &Ss[(wq*16)*132 + ks*8], 132);
                wmma::load_matrix_sync(vb[0], &KVs[(ks*8)*68 + wd*32],      68);
                wmma::load_matrix_sync(vb[1], &KVs[(ks*8)*68 + wd*32 + 16], 68);
                wmma::mma_sync(o[0], pa, vb[0], o[0]);
                wmma::mma_sync(o[1], pa, vb[1], o[1]);
            }
        }
        __syncthreads();      // (d) PV done reading KVs(V)

        if(has_next){
            #pragma unroll
            for(int i=0;i<4;i++){
                int id = tid + i*512;
                int r = id >> 4, c4 = id & 15;
                float* d = &KVs[r*68 + c4*4];
                d[0]=to_tf32(kreg[i].x); d[1]=to_tf32(kreg[i].y);
                d[2]=to_tf32(kreg[i].z); d[3]=to_tf32(kreg[i].w);
            }
        }
    }

    // ---- finalize: divide by denom, store ----
    *(float4*)&aM[srow*20 + sqtr*4] =
        make_float4(1.0f/d_run, 1.0f/d_run, 1.0f/d_run, 1.0f/d_run);
    __syncthreads();
    {
        wmma::fragment<wmma::accumulator,16,16,8,float> ifr;
        wmma::load_matrix_sync(ifr, &aM[(wq*16)*20], 20, wmma::mem_row_major);
        #pragma unroll
        for(int e=0;e<ifr.num_elements;e++){
            o[0].x[e] *= ifr.x[e];
            o[1].x[e] *= ifr.x[e];
        }
        float* cb = ctx + ((size_t)(b*CNQ + q0 + wq*16))*CD + h*CDH + wd*32;
        wmma::store_matrix_sync(cb,      o[0], CD, wmma::mem_row_major);
        wmma::store_matrix_sync(cb + 16, o[1], CD, wmma::mem_row_major);
    }
}

// ------------------------- h+ffn, double LN, scatter-add -------------------
__global__ void k_final(const float* __restrict__ h, const float* __restrict__ t2,
                        const float* __restrict__ os, const float* __restrict__ ob,
                        const float* __restrict__ es, const float* __restrict__ eb,
                        const int*   __restrict__ qidx,
                        float* __restrict__ upd, float* __restrict__ outp){
    __shared__ float sbuf[16];
    int row = blockIdx.x;
    int b = row >> 9, p = row & (CNQ-1);
    int t = threadIdx.x;
    float x = h[(size_t)row*CD + t] + t2[(size_t)row*CD + t];

    float s1 = x, s2 = x*x;
    #pragma unroll
    for(int o=16;o>0;o>>=1){
        s1 += __shfl_xor_sync(0xffffffffu, s1, o);
        s2 += __shfl_xor_sync(0xffffffffu, s2, o);
    }
    if((t&31)==0){ sbuf[t>>5]=s1; sbuf[8+(t>>5)]=s2; }
    __syncthreads();
    s1=0.f; s2=0.f;
    #pragma unroll
    for(int i=0;i<8;i++){ s1+=sbuf[i]; s2+=sbuf[8+i]; }
    float mean = s1*(1.0f/CD);
    float var  = s2*(1.0f/CD) - mean*mean;
    float rstd = rsqrtf(var + 1e-5f);
    float y = (x-mean)*rstd*os[t] + ob[t];
    __syncthreads();

    s1 = y; s2 = y*y;
    #pragma unroll
    for(int o=16;o>0;o>>=1){
        s1 += __shfl_xor_sync(0xffffffffu, s1, o);
        s2 += __shfl_xor_sync(0xffffffffu, s2, o);
    }
    if((t&31)==0){ sbuf[t>>5]=s1; sbuf[8+(t>>5)]=s2; }
    __syncthreads();
    s1=0.f; s2=0.f;
    #pragma unroll
    for(int i=0;i<8;i++){ s1+=sbuf[i]; s2+=sbuf[8+i]; }
    float mean2 = s1*(1.0f/CD);
    float var2  = s2*(1.0f/CD) - mean2*mean2;
    float rstd2 = rsqrtf(var2 + 1e-5f);
    float res = (y-mean2)*rstd2*es[t] + eb[t];

    int node = qidx[p];
    size_t off = ((size_t)(b*CNS + node))*CD + t;
    atomicAdd(&upd[off],  res);
    atomicAdd(&outp[off], res);
}

// ------------------------- launch ------------------------------------------
extern "C" void kernel_launch(void* const* d_in, const int* in_sizes, int n_in,
                              void* d_out, int out_size){
    const float* in_upd  = (const float*)d_in[0];
    const float* emb     = (const float*)d_in[1];
    const float* maskL   = (const float*)d_in[2];
    const float* Wq      = (const float*)d_in[3];
    const float* Wk      = (const float*)d_in[4];
    const float* Wv      = (const float*)d_in[5];
    const float* Wo      = (const float*)d_in[6];
    const float* W1      = (const float*)d_in[7];
    const float* b1      = (const float*)d_in[8];
    const float* W2      = (const float*)d_in[9];
    const float* b2      = (const float*)d_in[10];
    const float* sys_s   = (const float*)d_in[11];
    const float* sys_b   = (const float*)d_in[12];
    const float* eff_s   = (const float*)d_in[13];
    const float* eff_b   = (const float*)d_in[14];
    const float* in_s    = (const float*)d_in[15];
    const float* in_b    = (const float*)d_in[16];
    const float* out_s   = (const float*)d_in[17];
    const float* out_b   = (const float*)d_in[18];
    const int*   qidxL   = (const int*)d_in[19];
    const int*   kidxL   = (const int*)d_in[20];
    float* outp = (float*)d_out;

    float *upd,*qb,*kb,*Qb,*Kb,*Vb,*ctx,*hb,*t1,*t2;
    uint32_t* mbits;
    cudaGetSymbolAddress((void**)&upd, g_upd);
    cudaGetSymbolAddress((void**)&qb,  g_q);
    cudaGetSymbolAddress((void**)&kb,  g_k);
    cudaGetSymbolAddress((void**)&Qb,  g_Qp);
    cudaGetSymbolAddress((void**)&Kb,  g_Kp);
    cudaGetSymbolAddress((void**)&Vb,  g_Vp);
    cudaGetSymbolAddress((void**)&ctx, g_ctx);
    cudaGetSymbolAddress((void**)&hb,  g_h);
    cudaGetSymbolAddress((void**)&t1,  g_t1);
    cudaGetSymbolAddress((void**)&t2,  g_t2);
    cudaGetSymbolAddress((void**)&mbits, g_mbits);

    const int flash_smem = FLASH_SMEM_FLOATS * (int)sizeof(float);  // ~144 KB
    cudaFuncSetAttribute(k_flash, cudaFuncAttributeMaxDynamicSharedMemorySize,
                         flash_smem);

    cudaMemsetAsync(d_out, 0, (size_t)out_size * sizeof(float));
    k_copy_upd<<<(CB*CNS*CD/4)/256, 256>>>((const float4*)in_upd);
    k_prep_mask<<<(CL*CNQ*NKW)/256, 256>>>(maskL);

    for(int l=0;l<CL;l++){
        const int* qi = qidxL + l*CNQ;
        const int* ki = kidxL + l*CNK;
        const uint32_t* mb = mbits + (size_t)l*CNQ*NKW;

        k_gather_ln<<<CB*CNQ, 256>>>(upd, emb, qi, sys_s, sys_b, qb, CNQ);
        k_gather_ln<<<CB*CNK, 256>>>(upd, emb, ki, sys_s, sys_b, kb, CNK);

        k_gemm_tc<<<dim3(CB*CNQ/128, 2), 256>>>(qb, Wq, nullptr, Qb, 0);
        k_gemm_tc<<<dim3(CB*CNK/128, 2), 256>>>(kb, Wk, nullptr, Kb, 0);
        k_gemm_tc<<<dim3(CB*CNK/128, 2), 256>>>(kb, Wv, nullptr, Vb, 0);

        k_flash<<<dim3(CNQ/128, CB*CH), 512, flash_smem>>>(Qb, Kb, Vb, mb, ctx);

        k_gemm_tc<<<dim3(CB*CNQ/128, 2), 256>>>(ctx, Wo, nullptr, t1, 0);
        k_ln  <<<CB*CNQ, 256>>>(t1, in_s, in_b, hb);

        k_gemm_tc<<<dim3(CB*CNQ/128, 2), 256>>>(hb, W1, b1, t1, 1);   // gelu
        k_gemm_tc<<<dim3(CB*CNQ/128, 2), 256>>>(t1, W2, b2, t2, 0);

        k_final<<<CB*CNQ, 256>>>(hb, t2, out_s, out_b, eff_s, eff_b,
                                 qi, upd, outp);
    }
}